// round 3
// baseline (speedup 1.0000x reference)
#include <cuda_runtime.h>
#include <cstdint>

#define TS   2048
#define TDK  64
#define TB   2
#define TH   16
#define TBH  (TB*TH)
#define CTX_ELEMS (TBH*TS*TDK)          /* 4,194,304  */
#define ATT_WORDS 4194304u              /* 134,217,728 bits / 32 */

// ---------------- device scratch (allowed: __device__ globals) --------------
__device__ float2   g_rowstats[TBH * TS];   // (max, 1/sum) per score row
__device__ unsigned g_keep[ATT_WORDS];      // dropout keep bits, 1 = keep

// ---------------- JAX threefry2x32 (key = (0, 42)) --------------------------
__device__ __forceinline__ void tf_round(unsigned& x0, unsigned& x1, int r) {
    x0 += x1;
    x1 = __funnelshift_l(x1, x1, r);   // rotl
    x1 ^= x0;
}

__device__ __forceinline__ void threefry2x32(unsigned c0, unsigned c1,
                                             unsigned& o0, unsigned& o1) {
    const unsigned k0 = 0u, k1 = 42u, k2 = 0x1BD11BDAu ^ 42u;
    unsigned x0 = c0 + k0, x1 = c1 + k1;
    tf_round(x0,x1,13); tf_round(x0,x1,15); tf_round(x0,x1,26); tf_round(x0,x1, 6);
    x0 += k1; x1 += k2 + 1u;
    tf_round(x0,x1,17); tf_round(x0,x1,29); tf_round(x0,x1,16); tf_round(x0,x1,24);
    x0 += k2; x1 += k0 + 2u;
    tf_round(x0,x1,13); tf_round(x0,x1,15); tf_round(x0,x1,26); tf_round(x0,x1, 6);
    x0 += k0; x1 += k1 + 3u;
    tf_round(x0,x1,17); tf_round(x0,x1,29); tf_round(x0,x1,16); tf_round(x0,x1,24);
    x0 += k1; x1 += k2 + 4u;
    tf_round(x0,x1,13); tf_round(x0,x1,15); tf_round(x0,x1,26); tf_round(x0,x1, 6);
    x0 += k2; x1 += k0 + 5u;
    o0 = x0; o1 = x1;
}

// Partitionable threefry (JAX >= 0.4.36 default):
//   bits[i] = lo32( prf ) with prf combine for 32-bit = bits1 ^ bits2,
//   counters (hi, lo) = (i >> 32, i & 0xffffffff) = (0, i) since N < 2^32.
// keep = uniform(bits) < 0.5  <=>  MSB(bits) == 0.
__global__ __launch_bounds__(256) void rng_kernel() {
    unsigned i = blockIdx.x * 256u + threadIdx.x;   // element index 0 .. 2^27-1
    unsigned o0, o1;
    threefry2x32(0u, i, o0, o1);
    unsigned bits = o0 ^ o1;
    unsigned word = __ballot_sync(0xffffffffu, (bits & 0x80000000u) == 0u);
    if ((threadIdx.x & 31u) == 0u) g_keep[i >> 5] = word;
}

// ---------------- K1: scores = Q K^T * 0.125 + (mask-1)*1e9 -----------------
__global__ __launch_bounds__(256) void scores_kernel(
    const float* __restrict__ Q, const float* __restrict__ Km,
    const float* __restrict__ mask, float* __restrict__ scores) {
    extern __shared__ float sm[];
    float* Qs = sm;             // [128][68]
    float* Ks = sm + 128 * 68;  // [128][68]

    const int bh    = blockIdx.z;
    const int b     = bh >> 4;
    const int qBase = blockIdx.y * 128;
    const int kBase = blockIdx.x * 128;
    const int tid   = threadIdx.x;

    const float* Qg = Q  + ((size_t)bh * TS + qBase) * TDK;
    const float* Kg = Km + ((size_t)bh * TS + kBase) * TDK;

#pragma unroll
    for (int i = 0; i < 8; i++) {
        int f = tid + i * 256, r = f >> 4, c4 = f & 15;
        *(float4*)(Qs + r * 68 + c4 * 4) = *(const float4*)(Qg + r * 64 + c4 * 4);
        *(float4*)(Ks + r * 68 + c4 * 4) = *(const float4*)(Kg + r * 64 + c4 * 4);
    }
    __syncthreads();

    const int tx = tid & 15, ty = tid >> 4;
    float acc[8][8];
#pragma unroll
    for (int i = 0; i < 8; i++)
#pragma unroll
        for (int j = 0; j < 8; j++) acc[i][j] = 0.f;

#pragma unroll 2
    for (int d4 = 0; d4 < 16; d4++) {
        float4 a[8];
#pragma unroll
        for (int j = 0; j < 8; j++)
            a[j] = *(const float4*)(Qs + (ty + 16 * j) * 68 + d4 * 4);
#pragma unroll
        for (int ik = 0; ik < 8; ik++) {
            float4 bb = *(const float4*)(Ks + (tx + 16 * ik) * 68 + d4 * 4);
#pragma unroll
            for (int iq = 0; iq < 8; iq++) {
                float v = acc[iq][ik];
                v = fmaf(a[iq].x, bb.x, v);
                v = fmaf(a[iq].y, bb.y, v);
                v = fmaf(a[iq].z, bb.z, v);
                v = fmaf(a[iq].w, bb.w, v);
                acc[iq][ik] = v;
            }
        }
    }

    const float* mrow = mask + (size_t)b * TS * TS;
#pragma unroll
    for (int iq = 0; iq < 8; iq++) {
        int q = qBase + ty + 16 * iq;
        size_t off  = ((size_t)bh * TS + q) * TS;
        size_t moff = (size_t)q * TS;
#pragma unroll
        for (int ik = 0; ik < 8; ik++) {
            int k = kBase + tx + 16 * ik;
            float mv = mrow[moff + k];
            scores[off + k] = acc[iq][ik] * 0.125f + (mv - 1.0f) * 1e9f;
        }
    }
}

// ---------------- K2: per-row (max, 1/sum(exp)) ------------------------------
__global__ __launch_bounds__(256) void rowstats_kernel(const float* __restrict__ scores) {
    int warp = threadIdx.x >> 5, lane = threadIdx.x & 31;
    size_t row = (size_t)blockIdx.x * 8 + warp;
    const float4* r4 = (const float4*)(scores + row * TS);
    float4 v[16];
    float m = -3.4e38f;
#pragma unroll
    for (int i = 0; i < 16; i++) {
        v[i] = r4[lane + 32 * i];
        m = fmaxf(m, fmaxf(fmaxf(v[i].x, v[i].y), fmaxf(v[i].z, v[i].w)));
    }
#pragma unroll
    for (int o = 16; o > 0; o >>= 1) m = fmaxf(m, __shfl_xor_sync(0xffffffffu, m, o));
    float s = 0.f;
#pragma unroll
    for (int i = 0; i < 16; i++)
        s += __expf(v[i].x - m) + __expf(v[i].y - m) +
             __expf(v[i].z - m) + __expf(v[i].w - m);
#pragma unroll
    for (int o = 16; o > 0; o >>= 1) s += __shfl_xor_sync(0xffffffffu, s, o);
    if (lane == 0) g_rowstats[row] = make_float2(m, 1.0f / s);
}

// ---------------- K3: attn write + dropout + (attn_drop @ V) ----------------
__global__ __launch_bounds__(256) void context_kernel(
    const float* __restrict__ V, float* __restrict__ attn, float* __restrict__ ctx) {
    extern __shared__ float sm[];
    float*  Ps = sm;                                // [128][68]
    float*  Vs = sm + 128 * 68;                     // [64][68]
    float2* st = (float2*)(sm + 128 * 68 + 64 * 68); // [128]

    const int bh    = blockIdx.z;
    const int qBase = blockIdx.x * 128;
    const int tid   = threadIdx.x;
    const int tx    = tid & 15, ty = tid >> 4;

    if (tid < 128) st[tid] = g_rowstats[(size_t)bh * TS + qBase + tid];
    __syncthreads();

    float4 acc[8];
#pragma unroll
    for (int j = 0; j < 8; j++) acc[j] = make_float4(0.f, 0.f, 0.f, 0.f);

    const float* Vg = V + (size_t)bh * TS * TDK;

    for (int c = 0; c < 32; c++) {
        int kBase = c * 64;
#pragma unroll
        for (int i = 0; i < 8; i++) {
            int f = tid + i * 256, r = f >> 4, c4 = f & 15;
            int q = qBase + r, k = kBase + c4 * 4;
            size_t off = ((size_t)bh * TS + q) * TS + k;
            float4 sv = *(const float4*)(attn + off);
            float2 s2 = st[r];
            float4 p;
            p.x = __expf(sv.x - s2.x) * s2.y;
            p.y = __expf(sv.y - s2.x) * s2.y;
            p.z = __expf(sv.z - s2.x) * s2.y;
            p.w = __expf(sv.w - s2.x) * s2.y;
            *(float4*)(attn + off) = p;               // normalized attn out
            unsigned w = g_keep[off >> 5];
            int bit = (int)(off & 31u);
            float4 pd;
            pd.x = ((w >> bit)       & 1u) ? p.x + p.x : 0.f;  // /(1-0.5) = *2
            pd.y = ((w >> (bit + 1)) & 1u) ? p.y + p.y : 0.f;
            pd.z = ((w >> (bit + 2)) & 1u) ? p.z + p.z : 0.f;
            pd.w = ((w >> (bit + 3)) & 1u) ? p.w + p.w : 0.f;
            *(float4*)(Ps + r * 68 + c4 * 4) = pd;
        }
#pragma unroll
        for (int i = 0; i < 4; i++) {
            int f = tid + i * 256, r = f >> 4, c4 = f & 15;
            *(float4*)(Vs + r * 68 + c4 * 4) =
                *(const float4*)(Vg + (size_t)(kBase + r) * TDK + c4 * 4);
        }
        __syncthreads();
#pragma unroll 8
        for (int kk = 0; kk < 64; kk++) {
            float4 bv = *(const float4*)(Vs + kk * 68 + tx * 4);
#pragma unroll
            for (int j = 0; j < 8; j++) {
                float av = Ps[(ty + 16 * j) * 68 + kk];
                acc[j].x = fmaf(av, bv.x, acc[j].x);
                acc[j].y = fmaf(av, bv.y, acc[j].y);
                acc[j].z = fmaf(av, bv.z, acc[j].z);
                acc[j].w = fmaf(av, bv.w, acc[j].w);
            }
        }
        __syncthreads();
    }

#pragma unroll
    for (int j = 0; j < 8; j++) {
        int q = qBase + ty + 16 * j;
        *(float4*)(ctx + ((size_t)bh * TS + q) * TDK + tx * 4) = acc[j];
    }
}

// ---------------- launch -----------------------------------------------------
extern "C" void kernel_launch(void* const* d_in, const int* in_sizes, int n_in,
                              void* d_out, int out_size) {
    const float* Q    = (const float*)d_in[0];
    const float* K    = (const float*)d_in[1];
    const float* V    = (const float*)d_in[2];
    const float* mask = (const float*)d_in[3];

    float* ctx  = (float*)d_out;            // context first (reference return order)
    float* attn = ctx + CTX_ELEMS;          // then attn; also used as scores scratch

    cudaFuncSetAttribute(scores_kernel,  cudaFuncAttributeMaxDynamicSharedMemorySize, 69632);
    cudaFuncSetAttribute(context_kernel, cudaFuncAttributeMaxDynamicSharedMemorySize, 53248);

    rng_kernel<<<524288, 256>>>();                                // keep-bit mask
    scores_kernel<<<dim3(16, 16, 32), 256, 69632>>>(Q, K, mask, attn);
    rowstats_kernel<<<8192, 256>>>(attn);
    context_kernel<<<dim3(16, 1, 32), 256, 53248>>>(V, attn, ctx);
}

// round 4
// speedup vs baseline: 1.0290x; 1.0290x over previous
#include <cuda_runtime.h>
#include <cstdint>

#define TS   2048
#define TDK  64
#define TB   2
#define TH   16
#define TBH  (TB*TH)
#define CTX_ELEMS (TBH*TS*TDK)          /* 4,194,304  */
#define ATT_WORDS 4194304u              /* 134,217,728 bits / 32 */

// ---------------- device scratch ---------------------------------------------
__device__ float2   g_part[TBH * TS * 16];  // per (row, ktile): (max, sumexp)
__device__ float2   g_rowstats[TBH * TS];   // (max, 1/sum) per score row
__device__ unsigned g_keep[ATT_WORDS];      // dropout keep bits, 1 = keep

// ---------------- packed f32x2 helpers ---------------------------------------
__device__ __forceinline__ unsigned long long fma2(unsigned long long a,
                                                   unsigned long long b,
                                                   unsigned long long c) {
    unsigned long long d;
    asm("fma.rn.f32x2 %0, %1, %2, %3;" : "=l"(d) : "l"(a), "l"(b), "l"(c));
    return d;
}
__device__ __forceinline__ unsigned long long dup2(float s) {
    unsigned long long d;
    asm("mov.b64 %0, {%1, %1};" : "=l"(d) : "f"(s));
    return d;
}
__device__ __forceinline__ float2 unpk(unsigned long long v) {
    float2 r;
    asm("mov.b64 {%0, %1}, %2;" : "=f"(r.x), "=f"(r.y) : "l"(v));
    return r;
}

// ---------------- JAX threefry2x32 (key = (0, 42)), partitionable ------------
__device__ __forceinline__ void tf_round(unsigned& x0, unsigned& x1, int r) {
    x0 += x1;
    x1 = __funnelshift_l(x1, x1, r);
    x1 ^= x0;
}
__device__ __forceinline__ unsigned tf_bits(unsigned c1) {
    const unsigned k0 = 0u, k1 = 42u, k2 = 0x1BD11BDAu ^ 42u;
    unsigned x0 = 0u + k0, x1 = c1 + k1;
    tf_round(x0,x1,13); tf_round(x0,x1,15); tf_round(x0,x1,26); tf_round(x0,x1, 6);
    x0 += k1; x1 += k2 + 1u;
    tf_round(x0,x1,17); tf_round(x0,x1,29); tf_round(x0,x1,16); tf_round(x0,x1,24);
    x0 += k2; x1 += k0 + 2u;
    tf_round(x0,x1,13); tf_round(x0,x1,15); tf_round(x0,x1,26); tf_round(x0,x1, 6);
    x0 += k0; x1 += k1 + 3u;
    tf_round(x0,x1,17); tf_round(x0,x1,29); tf_round(x0,x1,16); tf_round(x0,x1,24);
    x0 += k1; x1 += k2 + 4u;
    tf_round(x0,x1,13); tf_round(x0,x1,15); tf_round(x0,x1,26); tf_round(x0,x1, 6);
    x0 += k2; x1 += k0 + 5u;
    return x0 ^ x1;   // 32-bit combine
}

// ---------------- K1: fused scores + RNG + partial softmax stats -------------
// 128x128 tile. k-mapping: thread (tx,ty) owns k = tx*8+m (m 0..7, as 4 f32x2
// pairs), q = ty+16*iq. K tile stored d-major (Kt[d][k], pitch 132, bit-3/4
// swizzle) so b-operands load as packed pairs; Q row-major scalar broadcast.
__global__ __launch_bounds__(256) void scores_rng_kernel(
    const float* __restrict__ Q, const float* __restrict__ Km,
    const float* __restrict__ mask, float* __restrict__ scores) {
    extern __shared__ float sm[];
    float* Qs = sm;             // [128][68]
    float* Kt = sm + 128 * 68;  // [64][132]  d-major

    const int bh    = blockIdx.z;
    const int b     = bh >> 4;
    const int qBase = blockIdx.y * 128;
    const int kBase = blockIdx.x * 128;
    const int tid   = threadIdx.x;

    const float* Qg = Q  + ((size_t)bh * TS + qBase) * TDK;
    const float* Kg = Km + ((size_t)bh * TS + kBase) * TDK;

#pragma unroll
    for (int i = 0; i < 8; i++) {
        int f = tid + i * 256, r = f >> 4, c4 = f & 15;
        *(float4*)(Qs + r * 68 + c4 * 4) = *(const float4*)(Qg + r * 64 + c4 * 4);
        float4 kv = *(const float4*)(Kg + r * 64 + c4 * 4);
#pragma unroll
        for (int u = 0; u < 4; u++) {
            int d = c4 * 4 + u;
            int sig = (d >> 3) & 3;
            float vv = (u == 0) ? kv.x : (u == 1) ? kv.y : (u == 2) ? kv.z : kv.w;
            Kt[d * 132 + (r ^ (sig << 3))] = vv;
        }
    }
    __syncthreads();

    const int tx = tid & 15, ty = tid >> 4;

    // RNG assignment: thread owns 64 consecutive flat elements (2 keep words)
    const int rrow = tid >> 1, hh = tid & 1;
    const unsigned i0 = ((unsigned)(bh * TS + qBase + rrow)) * (unsigned)TS
                        + (unsigned)kBase + (unsigned)hh * 64u;
    unsigned w0 = 0u, w1 = 0u;

    unsigned long long acc[8][4];
#pragma unroll
    for (int j = 0; j < 8; j++)
#pragma unroll
        for (int p = 0; p < 4; p++) acc[j][p] = 0ull;

#pragma unroll
    for (int c = 0; c < 16; c++) {
        // --- 4 threefry draws interleaved with GEMM (alu pipe) ---
#pragma unroll
        for (int u = 0; u < 4; u++) {
            unsigned idx = (unsigned)(c * 4 + u);
            unsigned bit = (~tf_bits(i0 + idx)) >> 31;
            if (c * 4 + u < 32) w0 |= bit << (c * 4 + u);
            else                w1 |= bit << (c * 4 + u - 32);
        }
        // --- GEMM chunk: 4 d values ---
        float4 a4[8];
#pragma unroll
        for (int j = 0; j < 8; j++)
            a4[j] = *(const float4*)(Qs + (ty + 16 * j) * 68 + c * 4);
#pragma unroll
        for (int dd = 0; dd < 4; dd++) {
            int d = c * 4 + dd;
            int sig = (d >> 3) & 3;
            const float* kr = Kt + d * 132 + ((tx ^ sig) << 3);
            ulonglong2 b01 = *(const ulonglong2*)(kr);
            ulonglong2 b23 = *(const ulonglong2*)(kr + 4);
#pragma unroll
            for (int j = 0; j < 8; j++) {
                float as = (dd == 0) ? a4[j].x : (dd == 1) ? a4[j].y :
                           (dd == 2) ? a4[j].z : a4[j].w;
                unsigned long long a2 = dup2(as);
                acc[j][0] = fma2(a2, b01.x, acc[j][0]);
                acc[j][1] = fma2(a2, b01.y, acc[j][1]);
                acc[j][2] = fma2(a2, b23.x, acc[j][2]);
                acc[j][3] = fma2(a2, b23.y, acc[j][3]);
            }
        }
    }
    ((uint2*)g_keep)[i0 >> 6] = make_uint2(w0, w1);

    // --- epilogue: mask, store raw scores, per-row tile stats ---
    const float* mrow = mask + (size_t)b * TS * TS;
#pragma unroll
    for (int j = 0; j < 8; j++) {
        int q = qBase + ty + 16 * j;
        const float* mp = mrow + (size_t)q * TS + kBase + tx * 8;
        float4 m0 = *(const float4*)(mp);
        float4 m1 = *(const float4*)(mp + 4);
        float2 p0 = unpk(acc[j][0]), p1 = unpk(acc[j][1]);
        float2 p2 = unpk(acc[j][2]), p3 = unpk(acc[j][3]);
        float s0 = fmaf(p0.x, 0.125f, (m0.x - 1.0f) * 1e9f);
        float s1 = fmaf(p0.y, 0.125f, (m0.y - 1.0f) * 1e9f);
        float s2 = fmaf(p1.x, 0.125f, (m0.z - 1.0f) * 1e9f);
        float s3 = fmaf(p1.y, 0.125f, (m0.w - 1.0f) * 1e9f);
        float s4 = fmaf(p2.x, 0.125f, (m1.x - 1.0f) * 1e9f);
        float s5 = fmaf(p2.y, 0.125f, (m1.y - 1.0f) * 1e9f);
        float s6 = fmaf(p3.x, 0.125f, (m1.z - 1.0f) * 1e9f);
        float s7 = fmaf(p3.y, 0.125f, (m1.w - 1.0f) * 1e9f);
        float* op = scores + ((size_t)bh * TS + q) * TS + kBase + tx * 8;
        *(float4*)(op)     = make_float4(s0, s1, s2, s3);
        *(float4*)(op + 4) = make_float4(s4, s5, s6, s7);

        float mx = fmaxf(fmaxf(fmaxf(s0, s1), fmaxf(s2, s3)),
                         fmaxf(fmaxf(s4, s5), fmaxf(s6, s7)));
#pragma unroll
        for (int o = 8; o > 0; o >>= 1)
            mx = fmaxf(mx, __shfl_xor_sync(0xffffffffu, mx, o));
        float e = __expf(s0 - mx) + __expf(s1 - mx) + __expf(s2 - mx) +
                  __expf(s3 - mx) + __expf(s4 - mx) + __expf(s5 - mx) +
                  __expf(s6 - mx) + __expf(s7 - mx);
#pragma unroll
        for (int o = 8; o > 0; o >>= 1)
            e += __shfl_xor_sync(0xffffffffu, e, o);
        if (tx == 0)
            g_part[((size_t)bh * TS + q) * 16 + blockIdx.x] = make_float2(mx, e);
    }
}

// ---------------- K2: combine tile partials -> row (max, 1/sum) --------------
__global__ __launch_bounds__(256) void reduce_kernel() {
    unsigned row = blockIdx.x * 256u + threadIdx.x;   // 0 .. 65535
    const float2* pp = &g_part[(size_t)row * 16];
    float2 p[16];
#pragma unroll
    for (int t = 0; t < 16; t++) p[t] = pp[t];
    float m = p[0].x;
#pragma unroll
    for (int t = 1; t < 16; t++) m = fmaxf(m, p[t].x);
    float s = 0.f;
#pragma unroll
    for (int t = 0; t < 16; t++) s += p[t].y * __expf(p[t].x - m);
    g_rowstats[row] = make_float2(m, 1.0f / s);
}

// ---------------- K3: attn write + dropout + (attn_drop @ V), packed ---------
__global__ __launch_bounds__(256) void context_kernel(
    const float* __restrict__ V, float* __restrict__ attn, float* __restrict__ ctx) {
    extern __shared__ float sm[];
    float*  Ps = sm;                                 // [128][68]
    float*  Vs = sm + 128 * 68;                      // [64][68]
    float2* st = (float2*)(sm + 128 * 68 + 64 * 68); // [128]

    const int bh    = blockIdx.z;
    const int qBase = blockIdx.x * 128;
    const int tid   = threadIdx.x;
    const int tx    = tid & 15, ty = tid >> 4;

    if (tid < 128) st[tid] = g_rowstats[(size_t)bh * TS + qBase + tid];
    __syncthreads();

    unsigned long long acc2[8][2];
#pragma unroll
    for (int j = 0; j < 8; j++) { acc2[j][0] = 0ull; acc2[j][1] = 0ull; }

    const float* Vg = V + (size_t)bh * TS * TDK;

    for (int c = 0; c < 32; c++) {
        int kBase = c * 64;
#pragma unroll
        for (int i = 0; i < 8; i++) {
            int f = tid + i * 256, r = f >> 4, c4 = f & 15;
            int q = qBase + r, k = kBase + c4 * 4;
            size_t off = ((size_t)bh * TS + q) * TS + k;
            float4 sv = *(const float4*)(attn + off);
            float2 s2 = st[r];
            float4 p;
            p.x = __expf(sv.x - s2.x) * s2.y;
            p.y = __expf(sv.y - s2.x) * s2.y;
            p.z = __expf(sv.z - s2.x) * s2.y;
            p.w = __expf(sv.w - s2.x) * s2.y;
            *(float4*)(attn + off) = p;               // normalized attn out
            unsigned w = g_keep[off >> 5];
            int bit = (int)(off & 31u);
            float4 pd;
            pd.x = ((w >> bit)       & 1u) ? p.x + p.x : 0.f;   // /(1-0.5) = *2
            pd.y = ((w >> (bit + 1)) & 1u) ? p.y + p.y : 0.f;
            pd.z = ((w >> (bit + 2)) & 1u) ? p.z + p.z : 0.f;
            pd.w = ((w >> (bit + 3)) & 1u) ? p.w + p.w : 0.f;
            *(float4*)(Ps + r * 68 + c4 * 4) = pd;
        }
#pragma unroll
        for (int i = 0; i < 4; i++) {
            int f = tid + i * 256, r = f >> 4, c4 = f & 15;
            *(float4*)(Vs + r * 68 + c4 * 4) =
                *(const float4*)(Vg + (size_t)(kBase + r) * TDK + c4 * 4);
        }
        __syncthreads();
#pragma unroll
        for (int kk4 = 0; kk4 < 16; kk4++) {
            float4 av[8];
#pragma unroll
            for (int j = 0; j < 8; j++)
                av[j] = *(const float4*)(Ps + (ty + 16 * j) * 68 + kk4 * 4);
#pragma unroll
            for (int t = 0; t < 4; t++) {
                ulonglong2 bv = *(const ulonglong2*)(Vs + (kk4 * 4 + t) * 68 + tx * 4);
#pragma unroll
                for (int j = 0; j < 8; j++) {
                    float as = (t == 0) ? av[j].x : (t == 1) ? av[j].y :
                               (t == 2) ? av[j].z : av[j].w;
                    unsigned long long a2 = dup2(as);
                    acc2[j][0] = fma2(a2, bv.x, acc2[j][0]);
                    acc2[j][1] = fma2(a2, bv.y, acc2[j][1]);
                }
            }
        }
        __syncthreads();
    }

#pragma unroll
    for (int j = 0; j < 8; j++) {
        int q = qBase + ty + 16 * j;
        float2 lo = unpk(acc2[j][0]), hi = unpk(acc2[j][1]);
        *(float4*)(ctx + ((size_t)bh * TS + q) * TDK + tx * 4) =
            make_float4(lo.x, lo.y, hi.x, hi.y);
    }
}

// ---------------- launch -----------------------------------------------------
extern "C" void kernel_launch(void* const* d_in, const int* in_sizes, int n_in,
                              void* d_out, int out_size) {
    const float* Q    = (const float*)d_in[0];
    const float* K    = (const float*)d_in[1];
    const float* V    = (const float*)d_in[2];
    const float* mask = (const float*)d_in[3];

    float* ctx  = (float*)d_out;            // context first (reference return order)
    float* attn = ctx + CTX_ELEMS;          // then attn; also used as scores scratch

    cudaFuncSetAttribute(scores_rng_kernel, cudaFuncAttributeMaxDynamicSharedMemorySize, 69632);
    cudaFuncSetAttribute(context_kernel,    cudaFuncAttributeMaxDynamicSharedMemorySize, 53248);

    scores_rng_kernel<<<dim3(16, 16, 32), 256, 68608>>>(Q, K, mask, attn);
    reduce_kernel<<<256, 256>>>();
    context_kernel<<<dim3(16, 1, 32), 256, 53248>>>(V, attn, ctx);
}

// round 5
// speedup vs baseline: 1.1830x; 1.1496x over previous
#include <cuda_runtime.h>
#include <cstdint>

#define TS   2048
#define TDK  64
#define TB   2
#define TH   16
#define TBH  (TB*TH)
#define CTX_ELEMS (TBH*TS*TDK)          /* 4,194,304  */
#define ATT_WORDS 4194304u              /* 134,217,728 bits / 32 */

// ---------------- device scratch ---------------------------------------------
__device__ float2   g_part[TBH * TS * 16];  // per (row, ktile): (max, sumexp)
__device__ float2   g_rowstats[TBH * TS];   // (max, 1/sum) per score row
__device__ unsigned g_keep[ATT_WORDS];      // dropout keep bits, 1 = keep

// ---------------- packed f32x2 helpers ---------------------------------------
__device__ __forceinline__ unsigned long long fma2(unsigned long long a,
                                                   unsigned long long b,
                                                   unsigned long long c) {
    unsigned long long d;
    asm("fma.rn.f32x2 %0, %1, %2, %3;" : "=l"(d) : "l"(a), "l"(b), "l"(c));
    return d;
}
__device__ __forceinline__ unsigned long long dup2(float s) {
    unsigned long long d;
    asm("mov.b64 %0, {%1, %1};" : "=l"(d) : "f"(s));
    return d;
}
__device__ __forceinline__ float2 unpk(unsigned long long v) {
    float2 r;
    asm("mov.b64 {%0, %1}, %2;" : "=f"(r.x), "=f"(r.y) : "l"(v));
    return r;
}

// ---------------- JAX threefry2x32 (key = (0, 42)), partitionable ------------
__device__ __forceinline__ void tf_round(unsigned& x0, unsigned& x1, int r) {
    x0 += x1;
    x1 = __funnelshift_l(x1, x1, r);
    x1 ^= x0;
}
__device__ __forceinline__ unsigned tf_bits(unsigned c1) {
    const unsigned k0 = 0u, k1 = 42u, k2 = 0x1BD11BDAu ^ 42u;
    unsigned x0 = 0u + k0, x1 = c1 + k1;
    tf_round(x0,x1,13); tf_round(x0,x1,15); tf_round(x0,x1,26); tf_round(x0,x1, 6);
    x0 += k1; x1 += k2 + 1u;
    tf_round(x0,x1,17); tf_round(x0,x1,29); tf_round(x0,x1,16); tf_round(x0,x1,24);
    x0 += k2; x1 += k0 + 2u;
    tf_round(x0,x1,13); tf_round(x0,x1,15); tf_round(x0,x1,26); tf_round(x0,x1, 6);
    x0 += k0; x1 += k1 + 3u;
    tf_round(x0,x1,17); tf_round(x0,x1,29); tf_round(x0,x1,16); tf_round(x0,x1,24);
    x0 += k1; x1 += k2 + 4u;
    tf_round(x0,x1,13); tf_round(x0,x1,15); tf_round(x0,x1,26); tf_round(x0,x1, 6);
    x0 += k2; x1 += k0 + 5u;
    return x0 ^ x1;   // 32-bit combine
}

// ---------------- K1: fused scores + RNG + partial softmax stats -------------
// 128x128 tile, 256 threads, 2 blocks/SM. Thread (tx,ty) owns k = tx*8+m
// (4 f32x2 pairs), q = ty+16*iq. K tile d-major (Kt[d][k], pitch 132, xor
// swizzle); Q scalar broadcast from smem (no a-register prefetch -> low regs).
__global__ __launch_bounds__(256, 2) void scores_rng_kernel(
    const float* __restrict__ Q, const float* __restrict__ Km,
    const float* __restrict__ mask, float* __restrict__ scores) {
    extern __shared__ float sm[];
    float* Qs = sm;             // [128][68]
    float* Kt = sm + 128 * 68;  // [64][132]  d-major

    const int bh    = blockIdx.z;
    const int b     = bh >> 4;
    const int qBase = blockIdx.y * 128;
    const int kBase = blockIdx.x * 128;
    const int tid   = threadIdx.x;

    const float* Qg = Q  + ((size_t)bh * TS + qBase) * TDK;
    const float* Kg = Km + ((size_t)bh * TS + kBase) * TDK;

#pragma unroll
    for (int i = 0; i < 8; i++) {
        int f = tid + i * 256, r = f >> 4, c4 = f & 15;
        *(float4*)(Qs + r * 68 + c4 * 4) = *(const float4*)(Qg + r * 64 + c4 * 4);
        float4 kv = *(const float4*)(Kg + r * 64 + c4 * 4);
#pragma unroll
        for (int u = 0; u < 4; u++) {
            int d = c4 * 4 + u;
            int sig = (d >> 3) & 3;
            float vv = (u == 0) ? kv.x : (u == 1) ? kv.y : (u == 2) ? kv.z : kv.w;
            Kt[d * 132 + (r ^ (sig << 3))] = vv;
        }
    }
    __syncthreads();

    const int tx = tid & 15, ty = tid >> 4;

    // RNG: thread owns 64 consecutive flat elements (2 keep words)
    const int rrow = tid >> 1, hh = tid & 1;
    const unsigned i0 = ((unsigned)(bh * TS + qBase + rrow)) * (unsigned)TS
                        + (unsigned)kBase + (unsigned)hh * 64u;
    unsigned w0 = 0u, w1 = 0u;

    unsigned long long acc[8][4];
#pragma unroll
    for (int j = 0; j < 8; j++)
#pragma unroll
        for (int p = 0; p < 4; p++) acc[j][p] = 0ull;

    const float* Qrow = Qs + ty * 68;

#pragma unroll
    for (int c = 0; c < 16; c++) {
        // 4 threefry draws interleaved (alu pipe)
#pragma unroll
        for (int u = 0; u < 4; u++) {
            int e = c * 4 + u;
            unsigned bit = (~tf_bits(i0 + (unsigned)e)) >> 31;
            if (e < 32) w0 |= bit << e;
            else        w1 |= bit << (e - 32);
        }
        // GEMM chunk: 4 d values, b as packed pairs, a scalar broadcast
#pragma unroll
        for (int dd = 0; dd < 4; dd++) {
            int d = c * 4 + dd;
            int sig = (d >> 3) & 3;
            const float* kr = Kt + d * 132 + ((tx ^ sig) << 3);
            ulonglong2 b01 = *(const ulonglong2*)(kr);
            ulonglong2 b23 = *(const ulonglong2*)(kr + 4);
#pragma unroll
            for (int j = 0; j < 8; j++) {
                unsigned long long a2 = dup2(Qrow[16 * j * 68 + d]);
                acc[j][0] = fma2(a2, b01.x, acc[j][0]);
                acc[j][1] = fma2(a2, b01.y, acc[j][1]);
                acc[j][2] = fma2(a2, b23.x, acc[j][2]);
                acc[j][3] = fma2(a2, b23.y, acc[j][3]);
            }
        }
    }
    ((uint2*)g_keep)[i0 >> 6] = make_uint2(w0, w1);

    // epilogue: mask, store raw scores, per-row tile stats
    const float* mrow = mask + (size_t)b * TS * TS;
#pragma unroll
    for (int j = 0; j < 8; j++) {
        int q = qBase + ty + 16 * j;
        const float* mp = mrow + (size_t)q * TS + kBase + tx * 8;
        float4 m0 = *(const float4*)(mp);
        float4 m1 = *(const float4*)(mp + 4);
        float2 p0 = unpk(acc[j][0]), p1 = unpk(acc[j][1]);
        float2 p2 = unpk(acc[j][2]), p3 = unpk(acc[j][3]);
        float s0 = fmaf(p0.x, 0.125f, (m0.x - 1.0f) * 1e9f);
        float s1 = fmaf(p0.y, 0.125f, (m0.y - 1.0f) * 1e9f);
        float s2 = fmaf(p1.x, 0.125f, (m0.z - 1.0f) * 1e9f);
        float s3 = fmaf(p1.y, 0.125f, (m0.w - 1.0f) * 1e9f);
        float s4 = fmaf(p2.x, 0.125f, (m1.x - 1.0f) * 1e9f);
        float s5 = fmaf(p2.y, 0.125f, (m1.y - 1.0f) * 1e9f);
        float s6 = fmaf(p3.x, 0.125f, (m1.z - 1.0f) * 1e9f);
        float s7 = fmaf(p3.y, 0.125f, (m1.w - 1.0f) * 1e9f);
        float* op = scores + ((size_t)bh * TS + q) * TS + kBase + tx * 8;
        *(float4*)(op)     = make_float4(s0, s1, s2, s3);
        *(float4*)(op + 4) = make_float4(s4, s5, s6, s7);

        float mx = fmaxf(fmaxf(fmaxf(s0, s1), fmaxf(s2, s3)),
                         fmaxf(fmaxf(s4, s5), fmaxf(s6, s7)));
#pragma unroll
        for (int o = 8; o > 0; o >>= 1)
            mx = fmaxf(mx, __shfl_xor_sync(0xffffffffu, mx, o));
        float e = __expf(s0 - mx) + __expf(s1 - mx) + __expf(s2 - mx) +
                  __expf(s3 - mx) + __expf(s4 - mx) + __expf(s5 - mx) +
                  __expf(s6 - mx) + __expf(s7 - mx);
#pragma unroll
        for (int o = 8; o > 0; o >>= 1)
            e += __shfl_xor_sync(0xffffffffu, e, o);
        if (tx == 0)
            g_part[((size_t)bh * TS + q) * 16 + blockIdx.x] = make_float2(mx, e);
    }
}

// ---------------- K2: combine tile partials -> row (max, 1/sum) --------------
__global__ __launch_bounds__(256) void reduce_kernel() {
    unsigned row = blockIdx.x * 256u + threadIdx.x;   // 0 .. 65535
    const float2* pp = &g_part[(size_t)row * 16];
    float2 p[16];
#pragma unroll
    for (int t = 0; t < 16; t++) p[t] = pp[t];
    float m = p[0].x;
#pragma unroll
    for (int t = 1; t < 16; t++) m = fmaxf(m, p[t].x);
    float s = 0.f;
#pragma unroll
    for (int t = 0; t < 16; t++) s += p[t].y * __expf(p[t].x - m);
    g_rowstats[row] = make_float2(m, 1.0f / s);
}

// ---------------- K3: attn write + dropout + (attn_drop @ V), packed ---------
// 64q x 64dv tile, 256 threads, 3 blocks/SM. k in chunks of 64.
__global__ __launch_bounds__(256, 3) void context_kernel(
    const float* __restrict__ V, float* __restrict__ attn, float* __restrict__ ctx) {
    extern __shared__ float sm[];
    float*  Ps = sm;                                // [64][68]
    float*  Vs = sm + 64 * 68;                      // [64][68]
    float2* st = (float2*)(sm + 128 * 68);          // [64]

    const int bh    = blockIdx.z;
    const int qBase = blockIdx.x * 64;
    const int tid   = threadIdx.x;
    const int tx    = tid & 15, ty = tid >> 4;

    if (tid < 64) st[tid] = g_rowstats[(size_t)bh * TS + qBase + tid];
    __syncthreads();

    unsigned long long acc2[4][2];
#pragma unroll
    for (int j = 0; j < 4; j++) { acc2[j][0] = 0ull; acc2[j][1] = 0ull; }

    const float* Vg = V + (size_t)bh * TS * TDK;

    for (int c = 0; c < 32; c++) {
        int kBase = c * 64;
#pragma unroll
        for (int i = 0; i < 4; i++) {
            int f = tid + i * 256, r = f >> 4, c4 = f & 15;
            int q = qBase + r, k = kBase + c4 * 4;
            size_t off = ((size_t)bh * TS + q) * TS + k;
            float4 sv = *(const float4*)(attn + off);
            float2 s2 = st[r];
            float4 p;
            p.x = __expf(sv.x - s2.x) * s2.y;
            p.y = __expf(sv.y - s2.x) * s2.y;
            p.z = __expf(sv.z - s2.x) * s2.y;
            p.w = __expf(sv.w - s2.x) * s2.y;
            *(float4*)(attn + off) = p;               // normalized attn out
            unsigned w = g_keep[off >> 5];
            int bit = (int)(off & 31u);
            float4 pd;
            pd.x = ((w >> bit)       & 1u) ? p.x + p.x : 0.f;   // /(1-0.5) = *2
            pd.y = ((w >> (bit + 1)) & 1u) ? p.y + p.y : 0.f;
            pd.z = ((w >> (bit + 2)) & 1u) ? p.z + p.z : 0.f;
            pd.w = ((w >> (bit + 3)) & 1u) ? p.w + p.w : 0.f;
            *(float4*)(Ps + r * 68 + c4 * 4) = pd;

            *(float4*)(Vs + r * 68 + c4 * 4) =
                *(const float4*)(Vg + (size_t)(kBase + r) * TDK + c4 * 4);
        }
        __syncthreads();
#pragma unroll
        for (int kk4 = 0; kk4 < 16; kk4++) {
            float4 av[4];
#pragma unroll
            for (int j = 0; j < 4; j++)
                av[j] = *(const float4*)(Ps + (ty + 16 * j) * 68 + kk4 * 4);
#pragma unroll
            for (int t = 0; t < 4; t++) {
                ulonglong2 bv = *(const ulonglong2*)(Vs + (kk4 * 4 + t) * 68 + tx * 4);
#pragma unroll
                for (int j = 0; j < 4; j++) {
                    float as = (t == 0) ? av[j].x : (t == 1) ? av[j].y :
                               (t == 2) ? av[j].z : av[j].w;
                    unsigned long long a2 = dup2(as);
                    acc2[j][0] = fma2(a2, bv.x, acc2[j][0]);
                    acc2[j][1] = fma2(a2, bv.y, acc2[j][1]);
                }
            }
        }
        __syncthreads();
    }

#pragma unroll
    for (int j = 0; j < 4; j++) {
        int q = qBase + ty + 16 * j;
        float2 lo = unpk(acc2[j][0]), hi = unpk(acc2[j][1]);
        *(float4*)(ctx + ((size_t)bh * TS + q) * TDK + tx * 4) =
            make_float4(lo.x, lo.y, hi.x, hi.y);
    }
}

// ---------------- launch -----------------------------------------------------
extern "C" void kernel_launch(void* const* d_in, const int* in_sizes, int n_in,
                              void* d_out, int out_size) {
    const float* Q    = (const float*)d_in[0];
    const float* K    = (const float*)d_in[1];
    const float* V    = (const float*)d_in[2];
    const float* mask = (const float*)d_in[3];

    float* ctx  = (float*)d_out;            // context first (reference return order)
    float* attn = ctx + CTX_ELEMS;          // then attn; also used as scores scratch

    cudaFuncSetAttribute(scores_rng_kernel, cudaFuncAttributeMaxDynamicSharedMemorySize, 69632);
    cudaFuncSetAttribute(context_kernel,    cudaFuncAttributeMaxDynamicSharedMemorySize, 35328);

    scores_rng_kernel<<<dim3(16, 16, 32), 256, 68608>>>(Q, K, mask, attn);
    reduce_kernel<<<256, 256>>>();
    context_kernel<<<dim3(32, 1, 32), 256, 35328>>>(V, attn, ctx);
}

// round 6
// speedup vs baseline: 1.3035x; 1.1019x over previous
#include <cuda_runtime.h>
#include <cstdint>

#define TS   2048
#define TDK  64
#define TB   2
#define TH   16
#define TBH  (TB*TH)
#define CTX_ELEMS (TBH*TS*TDK)          /* 4,194,304  */
#define ATT_WORDS 4194304u              /* 134,217,728 bits / 32 */

// ---------------- device scratch ---------------------------------------------
__device__ float2   g_part[TBH * TS * 16];  // per (row, ktile): (max, sumexp)
__device__ float2   g_rowstats[TBH * TS];   // (max, 1/sum) per score row
__device__ unsigned g_keep[ATT_WORDS];      // dropout keep bits, 1 = keep

// ---------------- packed f32x2 helpers ---------------------------------------
__device__ __forceinline__ unsigned long long fma2(unsigned long long a,
                                                   unsigned long long b,
                                                   unsigned long long c) {
    unsigned long long d;
    asm("fma.rn.f32x2 %0, %1, %2, %3;" : "=l"(d) : "l"(a), "l"(b), "l"(c));
    return d;
}
__device__ __forceinline__ unsigned long long dup2(float s) {
    unsigned long long d;
    asm("mov.b64 %0, {%1, %1};" : "=l"(d) : "f"(s));
    return d;
}
__device__ __forceinline__ float2 unpk(unsigned long long v) {
    float2 r;
    asm("mov.b64 {%0, %1}, %2;" : "=f"(r.x), "=f"(r.y) : "l"(v));
    return r;
}

// ---------------- JAX threefry2x32 (key = (0, 42)), partitionable ------------
__device__ __forceinline__ void tf_round(unsigned& x0, unsigned& x1, int r) {
    x0 += x1;
    x1 = __funnelshift_l(x1, x1, r);
    x1 ^= x0;
}
__device__ __forceinline__ unsigned tf_bits(unsigned c1) {
    const unsigned k0 = 0u, k1 = 42u, k2 = 0x1BD11BDAu ^ 42u;
    unsigned x0 = 0u + k0, x1 = c1 + k1;
    tf_round(x0,x1,13); tf_round(x0,x1,15); tf_round(x0,x1,26); tf_round(x0,x1, 6);
    x0 += k1; x1 += k2 + 1u;
    tf_round(x0,x1,17); tf_round(x0,x1,29); tf_round(x0,x1,16); tf_round(x0,x1,24);
    x0 += k2; x1 += k0 + 2u;
    tf_round(x0,x1,13); tf_round(x0,x1,15); tf_round(x0,x1,26); tf_round(x0,x1, 6);
    x0 += k0; x1 += k1 + 3u;
    tf_round(x0,x1,17); tf_round(x0,x1,29); tf_round(x0,x1,16); tf_round(x0,x1,24);
    x0 += k1; x1 += k2 + 4u;
    tf_round(x0,x1,13); tf_round(x0,x1,15); tf_round(x0,x1,26); tf_round(x0,x1, 6);
    x0 += k2; x1 += k0 + 5u;
    return x0 ^ x1;   // 32-bit combine
}

// ---------------- K1: fused scores + RNG + partial softmax stats -------------
// 64q x 128k tile, 256 threads, 3 blocks/SM. Thread (tx,ty) owns k = tx*8+m
// (4 f32x2 pairs), q = ty+16*j (j<4). K tile d-major (Kt[d][k], pitch 132,
// xor swizzle); Q scalar broadcast from smem. 32 RNG draws/thread (1 word).
__global__ __launch_bounds__(256, 3) void scores_rng_kernel(
    const float* __restrict__ Q, const float* __restrict__ Km,
    const float* __restrict__ mask, float* __restrict__ scores) {
    extern __shared__ float sm[];
    float* Qs = sm;            // [64][68]
    float* Kt = sm + 64 * 68;  // [64][132]  d-major

    const int bh    = blockIdx.z;
    const int b     = bh >> 4;
    const int qBase = blockIdx.y * 64;
    const int kBase = blockIdx.x * 128;
    const int tid   = threadIdx.x;

    const float* Qg = Q  + ((size_t)bh * TS + qBase) * TDK;
    const float* Kg = Km + ((size_t)bh * TS + kBase) * TDK;

#pragma unroll
    for (int i = 0; i < 4; i++) {
        int f = tid + i * 256, r = f >> 4, c4 = f & 15;
        *(float4*)(Qs + r * 68 + c4 * 4) = *(const float4*)(Qg + r * 64 + c4 * 4);
    }
#pragma unroll
    for (int i = 0; i < 8; i++) {
        int f = tid + i * 256, r = f >> 4, c4 = f & 15;
        float4 kv = *(const float4*)(Kg + r * 64 + c4 * 4);
#pragma unroll
        for (int u = 0; u < 4; u++) {
            int d = c4 * 4 + u;
            int sig = (d >> 3) & 3;
            float vv = (u == 0) ? kv.x : (u == 1) ? kv.y : (u == 2) ? kv.z : kv.w;
            Kt[d * 132 + (r ^ (sig << 3))] = vv;
        }
    }
    __syncthreads();

    const int tx = tid & 15, ty = tid >> 4;

    // RNG: thread owns 32 consecutive flat elements (1 keep word)
    const unsigned i0 = ((unsigned)(bh * TS + qBase + (tid >> 2))) * (unsigned)TS
                        + (unsigned)kBase + (unsigned)(tid & 3) * 32u;
    unsigned w0 = 0u;

    unsigned long long acc[4][4];
#pragma unroll
    for (int j = 0; j < 4; j++)
#pragma unroll
        for (int p = 0; p < 4; p++) acc[j][p] = 0ull;

    const float* Qrow = Qs + ty * 68;

#pragma unroll
    for (int c = 0; c < 16; c++) {
        // 2 threefry draws interleaved (alu pipe)
#pragma unroll
        for (int u = 0; u < 2; u++) {
            int e = c * 2 + u;
            unsigned bit = (~tf_bits(i0 + (unsigned)e)) >> 31;
            w0 |= bit << e;
        }
        // GEMM chunk: 4 d values, b as packed pairs, a scalar broadcast
#pragma unroll
        for (int dd = 0; dd < 4; dd++) {
            int d = c * 4 + dd;
            int sig = (d >> 3) & 3;
            const float* kr = Kt + d * 132 + ((tx ^ sig) << 3);
            ulonglong2 b01 = *(const ulonglong2*)(kr);
            ulonglong2 b23 = *(const ulonglong2*)(kr + 4);
#pragma unroll
            for (int j = 0; j < 4; j++) {
                unsigned long long a2 = dup2(Qrow[16 * j * 68 + d]);
                acc[j][0] = fma2(a2, b01.x, acc[j][0]);
                acc[j][1] = fma2(a2, b01.y, acc[j][1]);
                acc[j][2] = fma2(a2, b23.x, acc[j][2]);
                acc[j][3] = fma2(a2, b23.y, acc[j][3]);
            }
        }
    }
    g_keep[i0 >> 5] = w0;

    // epilogue: mask, store raw scores, per-row tile stats
    const float* mrow = mask + (size_t)b * TS * TS;
#pragma unroll
    for (int j = 0; j < 4; j++) {
        int q = qBase + ty + 16 * j;
        const float* mp = mrow + (size_t)q * TS + kBase + tx * 8;
        float4 m0 = *(const float4*)(mp);
        float4 m1 = *(const float4*)(mp + 4);
        float2 p0 = unpk(acc[j][0]), p1 = unpk(acc[j][1]);
        float2 p2 = unpk(acc[j][2]), p3 = unpk(acc[j][3]);
        float s0 = fmaf(p0.x, 0.125f, (m0.x - 1.0f) * 1e9f);
        float s1 = fmaf(p0.y, 0.125f, (m0.y - 1.0f) * 1e9f);
        float s2 = fmaf(p1.x, 0.125f, (m0.z - 1.0f) * 1e9f);
        float s3 = fmaf(p1.y, 0.125f, (m0.w - 1.0f) * 1e9f);
        float s4 = fmaf(p2.x, 0.125f, (m1.x - 1.0f) * 1e9f);
        float s5 = fmaf(p2.y, 0.125f, (m1.y - 1.0f) * 1e9f);
        float s6 = fmaf(p3.x, 0.125f, (m1.z - 1.0f) * 1e9f);
        float s7 = fmaf(p3.y, 0.125f, (m1.w - 1.0f) * 1e9f);
        float* op = scores + ((size_t)bh * TS + q) * TS + kBase + tx * 8;
        *(float4*)(op)     = make_float4(s0, s1, s2, s3);
        *(float4*)(op + 4) = make_float4(s4, s5, s6, s7);

        float mx = fmaxf(fmaxf(fmaxf(s0, s1), fmaxf(s2, s3)),
                         fmaxf(fmaxf(s4, s5), fmaxf(s6, s7)));
#pragma unroll
        for (int o = 8; o > 0; o >>= 1)
            mx = fmaxf(mx, __shfl_xor_sync(0xffffffffu, mx, o));
        float e = __expf(s0 - mx) + __expf(s1 - mx) + __expf(s2 - mx) +
                  __expf(s3 - mx) + __expf(s4 - mx) + __expf(s5 - mx) +
                  __expf(s6 - mx) + __expf(s7 - mx);
#pragma unroll
        for (int o = 8; o > 0; o >>= 1)
            e += __shfl_xor_sync(0xffffffffu, e, o);
        if (tx == 0)
            g_part[((size_t)bh * TS + q) * 16 + blockIdx.x] = make_float2(mx, e);
    }
}

// ---------------- K2: combine tile partials -> row (max, 1/sum) --------------
__global__ __launch_bounds__(256) void reduce_kernel() {
    unsigned row = blockIdx.x * 256u + threadIdx.x;   // 0 .. 65535
    const float2* pp = &g_part[(size_t)row * 16];
    float2 p[16];
#pragma unroll
    for (int t = 0; t < 16; t++) p[t] = pp[t];
    float m = p[0].x;
#pragma unroll
    for (int t = 1; t < 16; t++) m = fmaxf(m, p[t].x);
    float s = 0.f;
#pragma unroll
    for (int t = 0; t < 16; t++) s += p[t].y * __expf(p[t].x - m);
    g_rowstats[row] = make_float2(m, 1.0f / s);
}

// ---------------- K3: attn write + dropout + (attn_drop @ V), packed ---------
// 64q x 64dv tile, 256 threads, 4 blocks/SM. k in chunks of 64.
__global__ __launch_bounds__(256, 4) void context_kernel(
    const float* __restrict__ V, float* __restrict__ attn, float* __restrict__ ctx) {
    extern __shared__ float sm[];
    float*  Ps = sm;                                // [64][68]
    float*  Vs = sm + 64 * 68;                      // [64][68]
    float2* st = (float2*)(sm + 128 * 68);          // [64]

    const int bh    = blockIdx.z;
    const int qBase = blockIdx.x * 64;
    const int tid   = threadIdx.x;
    const int tx    = tid & 15, ty = tid >> 4;

    if (tid < 64) st[tid] = g_rowstats[(size_t)bh * TS + qBase + tid];
    __syncthreads();

    unsigned long long acc2[4][2];
#pragma unroll
    for (int j = 0; j < 4; j++) { acc2[j][0] = 0ull; acc2[j][1] = 0ull; }

    const float* Vg = V + (size_t)bh * TS * TDK;

    for (int c = 0; c < 32; c++) {
        int kBase = c * 64;
#pragma unroll
        for (int i = 0; i < 4; i++) {
            int f = tid + i * 256, r = f >> 4, c4 = f & 15;
            int q = qBase + r, k = kBase + c4 * 4;
            size_t off = ((size_t)bh * TS + q) * TS + k;
            float4 sv = *(const float4*)(attn + off);
            float2 s2 = st[r];
            float4 p;
            p.x = __expf(sv.x - s2.x) * s2.y;
            p.y = __expf(sv.y - s2.x) * s2.y;
            p.z = __expf(sv.z - s2.x) * s2.y;
            p.w = __expf(sv.w - s2.x) * s2.y;
            *(float4*)(attn + off) = p;               // normalized attn out
            unsigned w = g_keep[off >> 5];
            int bit = (int)(off & 31u);
            float4 pd;
            pd.x = ((w >> bit)       & 1u) ? p.x + p.x : 0.f;   // /(1-0.5) = *2
            pd.y = ((w >> (bit + 1)) & 1u) ? p.y + p.y : 0.f;
            pd.z = ((w >> (bit + 2)) & 1u) ? p.z + p.z : 0.f;
            pd.w = ((w >> (bit + 3)) & 1u) ? p.w + p.w : 0.f;
            *(float4*)(Ps + r * 68 + c4 * 4) = pd;

            *(float4*)(Vs + r * 68 + c4 * 4) =
                *(const float4*)(Vg + (size_t)(kBase + r) * TDK + c4 * 4);
        }
        __syncthreads();
#pragma unroll
        for (int kk4 = 0; kk4 < 16; kk4++) {
            float4 av[4];
#pragma unroll
            for (int j = 0; j < 4; j++)
                av[j] = *(const float4*)(Ps + (ty + 16 * j) * 68 + kk4 * 4);
#pragma unroll
            for (int t = 0; t < 4; t++) {
                ulonglong2 bv = *(const ulonglong2*)(Vs + (kk4 * 4 + t) * 68 + tx * 4);
#pragma unroll
                for (int j = 0; j < 4; j++) {
                    float as = (t == 0) ? av[j].x : (t == 1) ? av[j].y :
                               (t == 2) ? av[j].z : av[j].w;
                    unsigned long long a2 = dup2(as);
                    acc2[j][0] = fma2(a2, bv.x, acc2[j][0]);
                    acc2[j][1] = fma2(a2, bv.y, acc2[j][1]);
                }
            }
        }
        __syncthreads();
    }

#pragma unroll
    for (int j = 0; j < 4; j++) {
        int q = qBase + ty + 16 * j;
        float2 lo = unpk(acc2[j][0]), hi = unpk(acc2[j][1]);
        *(float4*)(ctx + ((size_t)bh * TS + q) * TDK + tx * 4) =
            make_float4(lo.x, lo.y, hi.x, hi.y);
    }
}

// ---------------- launch -----------------------------------------------------
extern "C" void kernel_launch(void* const* d_in, const int* in_sizes, int n_in,
                              void* d_out, int out_size) {
    const float* Q    = (const float*)d_in[0];
    const float* K    = (const float*)d_in[1];
    const float* V    = (const float*)d_in[2];
    const float* mask = (const float*)d_in[3];

    float* ctx  = (float*)d_out;            // context first (reference return order)
    float* attn = ctx + CTX_ELEMS;          // then attn; also used as scores scratch

    cudaFuncSetAttribute(scores_rng_kernel, cudaFuncAttributeMaxDynamicSharedMemorySize, 51200);
    cudaFuncSetAttribute(context_kernel,    cudaFuncAttributeMaxDynamicSharedMemorySize, 35328);

    scores_rng_kernel<<<dim3(16, 32, 32), 256, 51200>>>(Q, K, mask, attn);
    reduce_kernel<<<256, 256>>>();
    context_kernel<<<dim3(32, 1, 32), 256, 35328>>>(V, attn, ctx);
}

// round 7
// speedup vs baseline: 1.4076x; 1.0799x over previous
#include <cuda_runtime.h>
#include <cstdint>

#define TS   2048
#define TDK  64
#define TB   2
#define TH   16
#define TBH  (TB*TH)
#define CTX_ELEMS (TBH*TS*TDK)          /* 4,194,304  */

// ---------------- device scratch ---------------------------------------------
__device__ float2 g_part[TBH * TS * 16];  // per (row, ktile): (max, sumexp)
__device__ float2 g_rowstats[TBH * TS];   // (max, 1/sum) per score row

// ---------------- packed f32x2 helpers ---------------------------------------
__device__ __forceinline__ unsigned long long fma2(unsigned long long a,
                                                   unsigned long long b,
                                                   unsigned long long c) {
    unsigned long long d;
    asm("fma.rn.f32x2 %0, %1, %2, %3;" : "=l"(d) : "l"(a), "l"(b), "l"(c));
    return d;
}
__device__ __forceinline__ unsigned long long dup2(float s) {
    unsigned long long d;
    asm("mov.b64 %0, {%1, %1};" : "=l"(d) : "f"(s));
    return d;
}
__device__ __forceinline__ float2 unpk(unsigned long long v) {
    float2 r;
    asm("mov.b64 {%0, %1}, %2;" : "=f"(r.x), "=f"(r.y) : "l"(v));
    return r;
}

// ---------------- JAX threefry2x32 (key = (0, 42)), partitionable ------------
__device__ __forceinline__ void tf_round(unsigned& x0, unsigned& x1, int r) {
    x0 += x1;
    x1 = __funnelshift_l(x1, x1, r);
    x1 ^= x0;
}
__device__ __forceinline__ unsigned tf_bits(unsigned c1) {
    const unsigned k0 = 0u, k1 = 42u, k2 = 0x1BD11BDAu ^ 42u;
    unsigned x0 = 0u + k0, x1 = c1 + k1;
    tf_round(x0,x1,13); tf_round(x0,x1,15); tf_round(x0,x1,26); tf_round(x0,x1, 6);
    x0 += k1; x1 += k2 + 1u;
    tf_round(x0,x1,17); tf_round(x0,x1,29); tf_round(x0,x1,16); tf_round(x0,x1,24);
    x0 += k2; x1 += k0 + 2u;
    tf_round(x0,x1,13); tf_round(x0,x1,15); tf_round(x0,x1,26); tf_round(x0,x1, 6);
    x0 += k0; x1 += k1 + 3u;
    tf_round(x0,x1,17); tf_round(x0,x1,29); tf_round(x0,x1,16); tf_round(x0,x1,24);
    x0 += k1; x1 += k2 + 4u;
    tf_round(x0,x1,13); tf_round(x0,x1,15); tf_round(x0,x1,26); tf_round(x0,x1, 6);
    x0 += k2; x1 += k0 + 5u;
    return x0 ^ x1;   // 32-bit combine
}

// keep bit for flat attn element index e (uniform(bits) < 0.5 <=> MSB clear)
__device__ __forceinline__ float keep2x(unsigned e) {
    // returns 2.0 if kept (inverse keep-prob), 0.0 if dropped
    return ((~tf_bits(e)) >> 31) ? 2.0f : 0.0f;
}

// ---------------- K1: scores = Q K^T * 0.125 + (mask-1)*1e9 + tile stats -----
// 64q x 128k tile, 256 threads, 3 blocks/SM. Warp layout: tx=tid&31 owns
// k = tx*4 (2 f32x2 pairs) -> a warp covers the full 128-k extent exactly once
// (no duplicate b-loads). ty=tid>>5; q = ty + 8j (j<8). K tile d-major with
// float4-granular xor swizzle; Q read as single-address float4 broadcast.
__global__ __launch_bounds__(256, 3) void scores_kernel(
    const float* __restrict__ Q, const float* __restrict__ Km,
    const float* __restrict__ mask, float* __restrict__ scores) {
    extern __shared__ float sm[];
    float* Qs = sm;            // [64][68]
    float* Kt = sm + 64 * 68;  // [64][132]  d-major

    const int bh    = blockIdx.z;
    const int b     = bh >> 4;
    const int qBase = blockIdx.y * 64;
    const int kBase = blockIdx.x * 128;
    const int tid   = threadIdx.x;

    const float* Qg = Q  + ((size_t)bh * TS + qBase) * TDK;
    const float* Kg = Km + ((size_t)bh * TS + kBase) * TDK;

#pragma unroll
    for (int i = 0; i < 4; i++) {
        int f = tid + i * 256, r = f >> 4, c4 = f & 15;
        *(float4*)(Qs + r * 68 + c4 * 4) = *(const float4*)(Qg + r * 64 + c4 * 4);
    }
#pragma unroll
    for (int i = 0; i < 8; i++) {
        int f = tid + i * 256, r = f >> 4, c4 = f & 15;   // r = k row 0..127
        float4 kv = *(const float4*)(Kg + r * 64 + c4 * 4);
#pragma unroll
        for (int u = 0; u < 4; u++) {
            int d = c4 * 4 + u;
            int s = ((d >> 3) & 3) << 3;
            float vv = (u == 0) ? kv.x : (u == 1) ? kv.y : (u == 2) ? kv.z : kv.w;
            Kt[d * 132 + (r ^ s)] = vv;
        }
    }
    __syncthreads();

    const int tx = tid & 31, ty = tid >> 5;

    unsigned long long acc[8][2];
#pragma unroll
    for (int j = 0; j < 8; j++) { acc[j][0] = 0ull; acc[j][1] = 0ull; }

#pragma unroll
    for (int c = 0; c < 16; c++) {
        ulonglong2 bb[4];
#pragma unroll
        for (int dd = 0; dd < 4; dd++) {
            int d = c * 4 + dd;
            int s = ((d >> 3) & 3) << 3;
            bb[dd] = *(const ulonglong2*)(Kt + d * 132 + ((tx << 2) ^ s));
        }
#pragma unroll
        for (int j = 0; j < 8; j++) {
            float4 a = *(const float4*)(Qs + (ty + 8 * j) * 68 + c * 4);
            unsigned long long a0 = dup2(a.x), a1 = dup2(a.y);
            unsigned long long a2 = dup2(a.z), a3 = dup2(a.w);
            acc[j][0] = fma2(a0, bb[0].x, acc[j][0]);
            acc[j][1] = fma2(a0, bb[0].y, acc[j][1]);
            acc[j][0] = fma2(a1, bb[1].x, acc[j][0]);
            acc[j][1] = fma2(a1, bb[1].y, acc[j][1]);
            acc[j][0] = fma2(a2, bb[2].x, acc[j][0]);
            acc[j][1] = fma2(a2, bb[2].y, acc[j][1]);
            acc[j][0] = fma2(a3, bb[3].x, acc[j][0]);
            acc[j][1] = fma2(a3, bb[3].y, acc[j][1]);
        }
    }

    // epilogue: mask, store scores, per-(row,ktile) stats (full-warp reduce)
    const float* mrow = mask + (size_t)b * TS * TS;
#pragma unroll
    for (int j = 0; j < 8; j++) {
        int q = qBase + ty + 8 * j;
        float4 m0 = *(const float4*)(mrow + (size_t)q * TS + kBase + tx * 4);
        float2 p0 = unpk(acc[j][0]), p1 = unpk(acc[j][1]);
        float s0 = fmaf(p0.x, 0.125f, (m0.x - 1.0f) * 1e9f);
        float s1 = fmaf(p0.y, 0.125f, (m0.y - 1.0f) * 1e9f);
        float s2 = fmaf(p1.x, 0.125f, (m0.z - 1.0f) * 1e9f);
        float s3 = fmaf(p1.y, 0.125f, (m0.w - 1.0f) * 1e9f);
        *(float4*)(scores + ((size_t)bh * TS + q) * TS + kBase + tx * 4) =
            make_float4(s0, s1, s2, s3);

        float mx = fmaxf(fmaxf(s0, s1), fmaxf(s2, s3));
#pragma unroll
        for (int o = 16; o > 0; o >>= 1)
            mx = fmaxf(mx, __shfl_xor_sync(0xffffffffu, mx, o));
        float e = __expf(s0 - mx) + __expf(s1 - mx) +
                  __expf(s2 - mx) + __expf(s3 - mx);
#pragma unroll
        for (int o = 16; o > 0; o >>= 1)
            e += __shfl_xor_sync(0xffffffffu, e, o);
        if (tx == 0)
            g_part[((size_t)bh * TS + q) * 16 + blockIdx.x] = make_float2(mx, e);
    }
}

// ---------------- K2: combine tile partials -> row (max, 1/sum) --------------
__global__ __launch_bounds__(256) void reduce_kernel() {
    unsigned row = blockIdx.x * 256u + threadIdx.x;   // 0 .. 65535
    const float2* pp = &g_part[(size_t)row * 16];
    float2 p[16];
#pragma unroll
    for (int t = 0; t < 16; t++) p[t] = pp[t];
    float m = p[0].x;
#pragma unroll
    for (int t = 1; t < 16; t++) m = fmaxf(m, p[t].x);
    float s = 0.f;
#pragma unroll
    for (int t = 0; t < 16; t++) s += p[t].y * __expf(p[t].x - m);
    g_rowstats[row] = make_float2(m, 1.0f / s);
}

// ---------------- K3: attn write + inline-RNG dropout + (P_drop @ V) ---------
// 64q x 64dv tile, 256 threads, 3 blocks/SM. k in chunks of 64. The threefry
// keep bits are drawn inline by the thread that stages each score float4
// (alu pipe overlaps the f32x2 GEMM on the fma pipe).
__global__ __launch_bounds__(256, 3) void context_kernel(
    const float* __restrict__ V, float* __restrict__ attn, float* __restrict__ ctx) {
    extern __shared__ float sm[];
    float*  Ps = sm;                                // [64][68]
    float*  Vs = sm + 64 * 68;                      // [64][68]
    float2* st = (float2*)(sm + 128 * 68);          // [64]

    const int bh    = blockIdx.z;
    const int qBase = blockIdx.x * 64;
    const int tid   = threadIdx.x;
    const int tx    = tid & 15, ty = tid >> 4;

    if (tid < 64) st[tid] = g_rowstats[(size_t)bh * TS + qBase + tid];
    __syncthreads();

    unsigned long long acc2[4][2];
#pragma unroll
    for (int j = 0; j < 4; j++) { acc2[j][0] = 0ull; acc2[j][1] = 0ull; }

    const float* Vg = V + (size_t)bh * TS * TDK;

    for (int c = 0; c < 32; c++) {
        int kBase = c * 64;
#pragma unroll
        for (int i = 0; i < 4; i++) {
            int f = tid + i * 256, r = f >> 4, c4 = f & 15;
            int q = qBase + r, k = kBase + c4 * 4;
            size_t off = ((size_t)bh * TS + q) * TS + k;
            unsigned e0 = ((unsigned)(bh * TS + q)) * (unsigned)TS + (unsigned)k;
            float4 sv = *(const float4*)(attn + off);
            float2 s2 = st[r];
            float4 p;
            p.x = __expf(sv.x - s2.x) * s2.y;
            p.y = __expf(sv.y - s2.x) * s2.y;
            p.z = __expf(sv.z - s2.x) * s2.y;
            p.w = __expf(sv.w - s2.x) * s2.y;
            *(float4*)(attn + off) = p;               // normalized attn out
            float4 pd;
            pd.x = p.x * keep2x(e0);
            pd.y = p.y * keep2x(e0 + 1u);
            pd.z = p.z * keep2x(e0 + 2u);
            pd.w = p.w * keep2x(e0 + 3u);
            *(float4*)(Ps + r * 68 + c4 * 4) = pd;

            *(float4*)(Vs + r * 68 + c4 * 4) =
                *(const float4*)(Vg + (size_t)(kBase + r) * TDK + c4 * 4);
        }
        __syncthreads();
#pragma unroll
        for (int kk4 = 0; kk4 < 16; kk4++) {
            float4 av[4];
#pragma unroll
            for (int j = 0; j < 4; j++)
                av[j] = *(const float4*)(Ps + (ty + 16 * j) * 68 + kk4 * 4);
#pragma unroll
            for (int t = 0; t < 4; t++) {
                ulonglong2 bv = *(const ulonglong2*)(Vs + (kk4 * 4 + t) * 68 + tx * 4);
#pragma unroll
                for (int j = 0; j < 4; j++) {
                    float as = (t == 0) ? av[j].x : (t == 1) ? av[j].y :
                               (t == 2) ? av[j].z : av[j].w;
                    unsigned long long a2 = dup2(as);
                    acc2[j][0] = fma2(a2, bv.x, acc2[j][0]);
                    acc2[j][1] = fma2(a2, bv.y, acc2[j][1]);
                }
            }
        }
        __syncthreads();
    }

#pragma unroll
    for (int j = 0; j < 4; j++) {
        int q = qBase + ty + 16 * j;
        float2 lo = unpk(acc2[j][0]), hi = unpk(acc2[j][1]);
        *(float4*)(ctx + ((size_t)bh * TS + q) * TDK + tx * 4) =
            make_float4(lo.x, lo.y, hi.x, hi.y);
    }
}

// ---------------- launch -----------------------------------------------------
extern "C" void kernel_launch(void* const* d_in, const int* in_sizes, int n_in,
                              void* d_out, int out_size) {
    const float* Q    = (const float*)d_in[0];
    const float* K    = (const float*)d_in[1];
    const float* V    = (const float*)d_in[2];
    const float* mask = (const float*)d_in[3];

    float* ctx  = (float*)d_out;            // context first (reference return order)
    float* attn = ctx + CTX_ELEMS;          // then attn; also used as scores scratch

    cudaFuncSetAttribute(scores_kernel,  cudaFuncAttributeMaxDynamicSharedMemorySize, 51200);
    cudaFuncSetAttribute(context_kernel, cudaFuncAttributeMaxDynamicSharedMemorySize, 35328);

    scores_kernel<<<dim3(16, 32, 32), 256, 51200>>>(Q, K, mask, attn);
    reduce_kernel<<<256, 256>>>();
    context_kernel<<<dim3(32, 1, 32), 256, 35328>>>(V, attn, ctx);
}